// round 8
// baseline (speedup 1.0000x reference)
#include <cuda_runtime.h>
#include <cuda_bf16.h>

// N=256 rows, W=512 positions, 3 channels, K=512 buckets.
#define N_ROWS 256
#define WLEN   512
#define K      512
#define BT     128           // 4 warps; 4 elements / thread; 4 buckets / thread
#define EPT    4
#define NW     4

// Cross-CTA scratch (device globals; zero-init, self-cleaning each run).
__device__ unsigned long long g_sums[N_ROWS * 9];  // [n][c*3 + {pp,nn,all}] int64 (2's-compl)
__device__ unsigned int      g_pq[N_ROWS * 3];     // p | q<<16 per (row,channel)
__device__ unsigned int      g_cnt[N_ROWS];        // atomicInc(...,11) wraps 11 -> 0

// One CTA per (row, channel). Per-WARP private count histograms (no zero
// barrier, warps flow independently), packed prefix scan over merged counts,
// per-element exact int64 contributions via avg-rank identity:
//   S_pp = 2Σ_pos v(2PP+cP-p), S_nn = 2Σ_neg v(2PN+cN-q), S_all = 2Σ v(..-W)
//   loss = S_pp/(p²-p+1) + (1-(S_all-S_pp-S_nn)/(2pq+1)) + S_nn/(q²-q+1)
// Per-warp partials go to global int64 REDG adds (order-independent ⇒
// deterministic); the 12th-arriving warp of each row computes the fp32 tail,
// resets the accumulators (replay-safe), and writes out[n].
__global__ void __launch_bounds__(BT)
icl_kernel(const float* __restrict__ a_gt, const float* __restrict__ s_gt,
           const float* __restrict__ e_gt, const float* __restrict__ a_h,
           const float* __restrict__ s_h,  const float* __restrict__ e_h,
           float* __restrict__ out)
{
    __shared__ int   cnt[NW][K];   // per-warp histograms: cntPos | cntNeg<<16
    __shared__ uint2 meta[K];      // {packed count, packed exclusive prefix}
    __shared__ int   warpAgg[NW];

    const int n    = blockIdx.x;
    const int c    = blockIdx.y;
    const int tid  = threadIdx.x;
    const int wid  = tid >> 5, lane = tid & 31;
    const int base = n * WLEN;

    const float* __restrict__ gt = (c == 0) ? a_gt : (c == 1) ? s_gt : e_gt;
    const float* __restrict__ ht = (c == 0) ? a_h  : (c == 1) ? s_h  : e_h;

    // ---- global loads first (2 LDG.128, front-batched) ----
    const float4 h4 = ((const float4*)(ht + base))[tid];
    const float4 g4 = ((const float4*)(gt + base))[tid];

    // ---- zero OWN warp's histogram segment (no CTA barrier!) ----
    {
        int4* seg = (int4*)cnt[wid];                 // 512 ints = 128 int4 / 32 lanes
        const int4 z = make_int4(0, 0, 0, 0);
        seg[lane] = z; seg[lane + 32] = z; seg[lane + 64] = z; seg[lane + 96] = z;
    }
    __syncwarp();

    const float h[EPT]  = { h4.x, h4.y, h4.z, h4.w };
    const float gv[EPT] = { g4.x, g4.y, g4.z, g4.w };

    int  b[EPT];
    bool f[EPT];
    #pragma unroll
    for (int i = 0; i < EPT; ++i) {
        int bi = (int)(h[i] * (float)K);
        b[i] = (bi > K - 1) ? (K - 1) : bi;
        f[i] = (gv[i] > 0.5f);
        atomicAdd(&cnt[wid][b[i]], f[i] ? 1 : (1 << 16));   // own segment only
    }
    __syncthreads();   // BAR 1: all histograms complete

    // ---- merge 4 segments + packed scan (4 buckets/thread, blocked) ----
    const int4 s0 = ((const int4*)cnt[0])[tid];
    const int4 s1 = ((const int4*)cnt[1])[tid];
    const int4 s2 = ((const int4*)cnt[2])[tid];
    const int4 s3 = ((const int4*)cnt[3])[tid];
    const int x[EPT] = { s0.x + s1.x + s2.x + s3.x,
                         s0.y + s1.y + s2.y + s3.y,
                         s0.z + s1.z + s2.z + s3.z,
                         s0.w + s1.w + s2.w + s3.w };
    const int tsum = x[0] + x[1] + x[2] + x[3];

    int incv = tsum;
    #pragma unroll
    for (int off = 1; off < 32; off <<= 1) {
        const int v = __shfl_up_sync(0xFFFFFFFFu, incv, off);
        if (lane >= off) incv += v;
    }
    if (lane == 31) warpAgg[wid] = incv;
    __syncthreads();   // BAR 2: warp aggregates visible

    int wbase = 0, total = 0;
    #pragma unroll
    for (int w = 0; w < NW; ++w) {
        const int v = warpAgg[w];
        if (w < wid) wbase += v;
        total += v;
    }
    int prefix = wbase + incv - tsum;            // packed exclusive prefix (bucket 4*tid)
    const int p = total & 0xFFFF;
    const int q = total >> 16;

    {
        uint4* meta4 = (uint4*)meta;
        const int pr0 = prefix;
        const int pr1 = pr0 + x[0];
        const int pr2 = pr1 + x[1];
        const int pr3 = pr2 + x[2];
        meta4[2 * tid]     = make_uint4((unsigned)x[0], (unsigned)pr0,
                                        (unsigned)x[1], (unsigned)pr1);
        meta4[2 * tid + 1] = make_uint4((unsigned)x[2], (unsigned)pr2,
                                        (unsigned)x[3], (unsigned)pr3);
    }
    __syncthreads();   // BAR 3: meta visible

    // ---- per-element exact int64 contributions ----
    long long app = 0, ann = 0, aall = 0;
    #pragma unroll
    for (int i = 0; i < EPT; ++i) {
        const uint2 m = meta[b[i]];
        const int cP = (int)(m.x & 0xFFFFu), cN = (int)(m.x >> 16);
        const int PP = (int)(m.y & 0xFFFFu), PN = (int)(m.y >> 16);
        const long long v = (long long)(int)(h[i] * 1073741824.0f);
        if (f[i]) app += v * (long long)(2 * PP + cP - p);
        else      ann += v * (long long)(2 * PN + cN - q);
        aall += v * (long long)(2 * (PP + PN) + (cP + cN) - WLEN);
    }

    // ---- intra-warp reduce only; warps retire independently ----
    #pragma unroll
    for (int off = 16; off > 0; off >>= 1) {
        app  += __shfl_down_sync(0xFFFFFFFFu, app,  off);
        ann  += __shfl_down_sync(0xFFFFFFFFu, ann,  off);
        aall += __shfl_down_sync(0xFFFFFFFFu, aall, off);
    }

    if (lane == 0) {
        if (wid == 0) g_pq[n * 3 + c] = (unsigned)(p | (q << 16));
        unsigned long long* gs = &g_sums[n * 9 + c * 3];
        atomicAdd(&gs[0], (unsigned long long)app);    // no-return int adds:
        atomicAdd(&gs[1], (unsigned long long)ann);    // order-independent,
        atomicAdd(&gs[2], (unsigned long long)aall);   // deterministic
        __threadfence();
        const unsigned int old = atomicInc(&g_cnt[n], 11u);  // wraps 11 -> 0
        if (old == 11u) {
            // 12th (last) warp of this row: fp32 tail for all 3 channels
            volatile unsigned long long* vg = &g_sums[n * 9];
            volatile unsigned int*       vq = &g_pq[n * 3];
            float rowLoss = 0.0f;
            #pragma unroll
            for (int cc = 0; cc < 3; ++cc) {
                const long long Ap = (long long)vg[cc * 3 + 0];
                const long long An = (long long)vg[cc * 3 + 1];
                const long long Aa = (long long)vg[cc * 3 + 2];
                vg[cc * 3 + 0] = 0ull;   // self-clean for graph replay
                vg[cc * 3 + 1] = 0ull;
                vg[cc * 3 + 2] = 0ull;
                const unsigned pq = vq[cc];
                const float pf = (float)(pq & 0xFFFFu);
                const float qf = (float)(pq >> 16);
                const long long Apn = Aa - Ap - An;          // exact
                const float sc = 2.0f / 1073741824.0f;
                const float t1 = (sc * (float)Ap)  / (pf * (pf - 1.0f) + 1.0f);
                const float t2 = 1.0f - (sc * (float)Apn) / (2.0f * pf * qf + 1.0f);
                const float t3 = (sc * (float)An)  / (qf * (qf - 1.0f) + 1.0f);
                rowLoss += t1 + t2 + t3;
            }
            out[n] = rowLoss;
        }
    }
}

extern "C" void kernel_launch(void* const* d_in, const int* in_sizes, int n_in,
                              void* d_out, int out_size)
{
    const float* a_gt = (const float*)d_in[0];
    const float* s_gt = (const float*)d_in[1];
    const float* e_gt = (const float*)d_in[2];
    const float* a_h  = (const float*)d_in[3];
    const float* s_h  = (const float*)d_in[4];
    const float* e_h  = (const float*)d_in[5];
    float* out = (float*)d_out;

    dim3 grid(N_ROWS, 3);
    icl_kernel<<<grid, BT>>>(a_gt, s_gt, e_gt, a_h, s_h, e_h, out);
}

// round 9
// speedup vs baseline: 1.4571x; 1.4571x over previous
#include <cuda_runtime.h>
#include <cuda_bf16.h>

// N=256 rows, W=512 positions, 3 channels, K=128 buckets.
#define N_ROWS 256
#define WLEN   512
#define K      128
#define BT     128           // 4 warps; 4 elements / thread
#define EPT    4
#define NW     4

// Cross-CTA combine scratch (device globals: no allocations allowed).
__device__ float        g_partial[N_ROWS * 3];
__device__ unsigned int g_cnt[N_ROWS];          // zero-init; atomicInc(...,2) self-resets

// One CTA per (row, channel). Count-only histogram into K=128 buckets
// (packed pos|neg<<16, one 32-bit smem atomic per element), SINGLE-WARP packed
// prefix scan, per-element exact int64 contributions via the avg-rank identity:
//   S_pp = 2Σ_pos v(2PP+cP-p), S_nn = 2Σ_neg v(2PN+cN-q), S_all = 2Σ v(..-W)
//   loss = S_pp/(p²-p+1) + (1-(S_all-S_pp-S_nn)/(2pq+1)) + S_nn/(q²-q+1)
// Last CTA of each row (fence + atomicInc) folds the 3 channel partials.
__global__ void __launch_bounds__(BT)
icl_kernel(const float* __restrict__ a_gt, const float* __restrict__ s_gt,
           const float* __restrict__ e_gt, const float* __restrict__ a_h,
           const float* __restrict__ s_h,  const float* __restrict__ e_h,
           float* __restrict__ out)
{
    __shared__ int       cnt[K];       // cntPos | cntNeg<<16
    __shared__ uint2     meta[K];      // {packed count, packed exclusive prefix}
    __shared__ int       totalSh;      // packed totals p | q<<16
    __shared__ long long red[3][NW];

    const int n    = blockIdx.x;
    const int c    = blockIdx.y;
    const int tid  = threadIdx.x;
    const int wid  = tid >> 5, lane = tid & 31;
    const int base = n * WLEN;

    const float* __restrict__ gt = (c == 0) ? a_gt : (c == 1) ? s_gt : e_gt;
    const float* __restrict__ ht = (c == 0) ? a_h  : (c == 1) ? s_h  : e_h;

    // ---- global loads first (2 LDG.128, front-batched) ----
    const float4 h4 = ((const float4*)(ht + base))[tid];
    const float4 g4 = ((const float4*)(gt + base))[tid];

    // ---- zero count histogram: exactly one STS.32 per thread ----
    cnt[tid] = 0;
    __syncthreads();                                   // BAR 1

    const float h[EPT]  = { h4.x, h4.y, h4.z, h4.w };
    const float gv[EPT] = { g4.x, g4.y, g4.z, g4.w };

    int  b[EPT];
    bool f[EPT];
    #pragma unroll
    for (int i = 0; i < EPT; ++i) {
        int bi = (int)(h[i] * (float)K);
        b[i] = (bi > K - 1) ? (K - 1) : bi;
        f[i] = (gv[i] > 0.5f);
        atomicAdd(&cnt[b[i]], f[i] ? 1 : (1 << 16));
    }
    __syncthreads();                                   // BAR 2: histogram complete

    // ---- single-warp packed scan over 128 buckets (warp 0 only) ----
    if (wid == 0) {
        const int4 x4 = ((const int4*)cnt)[lane];      // buckets 4*lane .. 4*lane+3
        const int tsum = x4.x + x4.y + x4.z + x4.w;

        int incv = tsum;
        #pragma unroll
        for (int off = 1; off < 32; off <<= 1) {
            const int v = __shfl_up_sync(0xFFFFFFFFu, incv, off);
            if (lane >= off) incv += v;
        }
        const int total = __shfl_sync(0xFFFFFFFFu, incv, 31);
        int pr = incv - tsum;                          // packed exclusive prefix

        uint4* meta4 = (uint4*)meta;
        const int pr0 = pr;
        const int pr1 = pr0 + x4.x;
        const int pr2 = pr1 + x4.y;
        const int pr3 = pr2 + x4.z;
        meta4[2 * lane]     = make_uint4((unsigned)x4.x, (unsigned)pr0,
                                         (unsigned)x4.y, (unsigned)pr1);
        meta4[2 * lane + 1] = make_uint4((unsigned)x4.z, (unsigned)pr2,
                                         (unsigned)x4.w, (unsigned)pr3);
        if (lane == 0) totalSh = total;
    }
    __syncthreads();                                   // BAR 3: meta + totals visible

    const int total = totalSh;
    const int p = total & 0xFFFF;
    const int q = total >> 16;

    // ---- per-element exact int64 contributions ----
    long long app = 0, ann = 0, aall = 0;
    #pragma unroll
    for (int i = 0; i < EPT; ++i) {
        const uint2 m = meta[b[i]];
        const int cP = (int)(m.x & 0xFFFFu), cN = (int)(m.x >> 16);
        const int PP = (int)(m.y & 0xFFFFu), PN = (int)(m.y >> 16);
        const long long v = (long long)(int)(h[i] * 1073741824.0f);
        if (f[i]) app += v * (long long)(2 * PP + cP - p);
        else      ann += v * (long long)(2 * PN + cN - q);
        aall += v * (long long)(2 * (PP + PN) + (cP + cN) - WLEN);
    }

    // ---- intra-warp reduce, 4-entry cross-warp via smem ----
    #pragma unroll
    for (int off = 16; off > 0; off >>= 1) {
        app  += __shfl_down_sync(0xFFFFFFFFu, app,  off);
        ann  += __shfl_down_sync(0xFFFFFFFFu, ann,  off);
        aall += __shfl_down_sync(0xFFFFFFFFu, aall, off);
    }
    if (lane == 0) { red[0][wid] = app; red[1][wid] = ann; red[2][wid] = aall; }
    __syncthreads();                                   // BAR 4

    // ---- fp32 tail + last-block combine ----
    if (tid == 0) {
        long long Ap = 0, An = 0, Aa = 0;
        #pragma unroll
        for (int w = 0; w < NW; ++w) { Ap += red[0][w]; An += red[1][w]; Aa += red[2][w]; }
        const long long Apn = Aa - Ap - An;            // exact: no cancellation risk
        const float sc = 2.0f / 1073741824.0f;
        const float pf = (float)p, qf = (float)q;
        const float c1 = (sc * (float)Ap)  / (pf * (pf - 1.0f) + 1.0f);
        const float c2 = 1.0f - (sc * (float)Apn) / (2.0f * pf * qf + 1.0f);
        const float c3 = (sc * (float)An)  / (qf * (qf - 1.0f) + 1.0f);

        g_partial[n * 3 + c] = c1 + c2 + c3;
        __threadfence();
        const unsigned int old = atomicInc(&g_cnt[n], 2u);   // wraps 2 -> 0 (replay-safe)
        if (old == 2u) {
            volatile float* gp = g_partial;
            out[n] = gp[n * 3 + 0] + gp[n * 3 + 1] + gp[n * 3 + 2];
        }
    }
}

extern "C" void kernel_launch(void* const* d_in, const int* in_sizes, int n_in,
                              void* d_out, int out_size)
{
    const float* a_gt = (const float*)d_in[0];
    const float* s_gt = (const float*)d_in[1];
    const float* e_gt = (const float*)d_in[2];
    const float* a_h  = (const float*)d_in[3];
    const float* s_h  = (const float*)d_in[4];
    const float* e_h  = (const float*)d_in[5];
    float* out = (float*)d_out;

    dim3 grid(N_ROWS, 3);
    icl_kernel<<<grid, BT>>>(a_gt, s_gt, e_gt, a_h, s_h, e_h, out);
}

// round 10
// speedup vs baseline: 1.4624x; 1.0036x over previous
#include <cuda_runtime.h>
#include <cuda_bf16.h>

// N=256 rows, W=512 positions, 3 channels, K=128 buckets.
#define N_ROWS 256
#define WLEN   512
#define K      128
#define BT     128           // 4 warps; 4 elements / thread
#define EPT    4
#define NW     4

// Cross-CTA combine scratch (device globals: no allocations allowed).
__device__ float        g_partial[N_ROWS * 3];
__device__ unsigned int g_cnt[N_ROWS];          // zero-init; atomicInc(...,2) self-resets

// One CTA per (row, channel). Per-warp count histograms (packed pos|neg<<16,
// no zero barrier), single-warp merge+scan producing PRE-BAKED float weights
// per bucket:  wP=2PP+cP-p, wN=2PN+cN-q, wAll=2(PP+PN)+cP+cN-W.
// Per element then: one LDS.128 + predicated FFMAs:
//   S_pp = 2Σ_pos h*wP,  S_nn = 2Σ_neg h*wN,  S_all = 2Σ h*wAll
//   loss = S_pp/(p²-p+1) + (1-(S_all-S_pp-S_nn)/(2pq+1)) + S_nn/(q²-q+1)
// Last CTA of each row (fence + atomicInc) folds the 3 channel partials.
__global__ void __launch_bounds__(BT)
icl_kernel(const float* __restrict__ a_gt, const float* __restrict__ s_gt,
           const float* __restrict__ e_gt, const float* __restrict__ a_h,
           const float* __restrict__ s_h,  const float* __restrict__ e_h,
           float* __restrict__ out)
{
    __shared__ int    cnt[NW][K];   // per-warp histograms: cntPos | cntNeg<<16
    __shared__ float4 metaf[K];     // {wP, wN, wAll, unused}
    __shared__ int    totalSh;      // packed totals p | q<<16
    __shared__ float  red[3][NW];

    const int n    = blockIdx.x;
    const int c    = blockIdx.y;
    const int tid  = threadIdx.x;
    const int wid  = tid >> 5, lane = tid & 31;
    const int base = n * WLEN;

    const float* __restrict__ gt = (c == 0) ? a_gt : (c == 1) ? s_gt : e_gt;
    const float* __restrict__ ht = (c == 0) ? a_h  : (c == 1) ? s_h  : e_h;

    // ---- global loads first (2 LDG.128, front-batched) ----
    const float4 h4 = ((const float4*)(ht + base))[tid];
    const float4 g4 = ((const float4*)(gt + base))[tid];

    // ---- zero OWN warp's histogram (1 STS.128/lane), warp-local sync only ----
    ((int4*)cnt[wid])[lane] = make_int4(0, 0, 0, 0);
    __syncwarp();

    const float h[EPT]  = { h4.x, h4.y, h4.z, h4.w };
    const float gv[EPT] = { g4.x, g4.y, g4.z, g4.w };

    int  b[EPT];
    bool f[EPT];
    #pragma unroll
    for (int i = 0; i < EPT; ++i) {
        int bi = (int)(h[i] * (float)K);
        b[i] = (bi > K - 1) ? (K - 1) : bi;
        f[i] = (gv[i] > 0.5f);
        atomicAdd(&cnt[wid][b[i]], f[i] ? 1 : (1 << 16));
    }
    __syncthreads();                                   // BAR 1: histograms done

    // ---- single-warp merge + packed scan + float-weight writeback ----
    if (wid == 0) {
        const int4 s0 = ((const int4*)cnt[0])[lane];
        const int4 s1 = ((const int4*)cnt[1])[lane];
        const int4 s2 = ((const int4*)cnt[2])[lane];
        const int4 s3 = ((const int4*)cnt[3])[lane];
        const int x[EPT] = { s0.x + s1.x + s2.x + s3.x,
                             s0.y + s1.y + s2.y + s3.y,
                             s0.z + s1.z + s2.z + s3.z,
                             s0.w + s1.w + s2.w + s3.w };
        const int tsum = x[0] + x[1] + x[2] + x[3];

        int incv = tsum;
        #pragma unroll
        for (int off = 1; off < 32; off <<= 1) {
            const int v = __shfl_up_sync(0xFFFFFFFFu, incv, off);
            if (lane >= off) incv += v;
        }
        const int total = __shfl_sync(0xFFFFFFFFu, incv, 31);
        const int p = total & 0xFFFF;
        const int q = total >> 16;

        int pr = incv - tsum;                          // packed exclusive prefix
        #pragma unroll
        for (int j = 0; j < EPT; ++j) {
            const int cP = x[j] & 0xFFFF, cN = x[j] >> 16;
            const int PP = pr & 0xFFFF,   PN = pr >> 16;
            metaf[4 * lane + j] = make_float4(
                (float)(2 * PP + cP - p),
                (float)(2 * PN + cN - q),
                (float)(2 * (PP + PN) + (cP + cN) - WLEN),
                0.0f);
            pr += x[j];
        }
        if (lane == 0) totalSh = total;
    }
    __syncthreads();                                   // BAR 2: weights visible

    // ---- per-element fp32 contributions: LDS.128 + 3 FFMA each ----
    float app = 0.0f, ann = 0.0f, aall = 0.0f;
    #pragma unroll
    for (int i = 0; i < EPT; ++i) {
        const float4 w = metaf[b[i]];
        if (f[i]) app += h[i] * w.x;
        else      ann += h[i] * w.y;
        aall += h[i] * w.z;
    }

    // ---- fp32 reduce: intra-warp shuffles, then 4-entry cross-warp ----
    #pragma unroll
    for (int off = 16; off > 0; off >>= 1) {
        app  += __shfl_down_sync(0xFFFFFFFFu, app,  off);
        ann  += __shfl_down_sync(0xFFFFFFFFu, ann,  off);
        aall += __shfl_down_sync(0xFFFFFFFFu, aall, off);
    }
    if (lane == 0) { red[0][wid] = app; red[1][wid] = ann; red[2][wid] = aall; }
    __syncthreads();                                   // BAR 3

    // ---- tail + last-block combine ----
    if (tid == 0) {
        float Ap = 0.0f, An = 0.0f, Aa = 0.0f;
        #pragma unroll
        for (int w = 0; w < NW; ++w) { Ap += red[0][w]; An += red[1][w]; Aa += red[2][w]; }
        const int total = totalSh;
        const float pf = (float)(total & 0xFFFF);
        const float qf = (float)(total >> 16);
        const float Apn = Aa - Ap - An;
        const float c1 = (2.0f * Ap)  / (pf * (pf - 1.0f) + 1.0f);
        const float c2 = 1.0f - (2.0f * Apn) / (2.0f * pf * qf + 1.0f);
        const float c3 = (2.0f * An)  / (qf * (qf - 1.0f) + 1.0f);

        g_partial[n * 3 + c] = c1 + c2 + c3;
        __threadfence();
        const unsigned int old = atomicInc(&g_cnt[n], 2u);   // wraps 2 -> 0 (replay-safe)
        if (old == 2u) {
            volatile float* gp = g_partial;
            out[n] = gp[n * 3 + 0] + gp[n * 3 + 1] + gp[n * 3 + 2];
        }
    }
}

extern "C" void kernel_launch(void* const* d_in, const int* in_sizes, int n_in,
                              void* d_out, int out_size)
{
    const float* a_gt = (const float*)d_in[0];
    const float* s_gt = (const float*)d_in[1];
    const float* e_gt = (const float*)d_in[2];
    const float* a_h  = (const float*)d_in[3];
    const float* s_h  = (const float*)d_in[4];
    const float* e_h  = (const float*)d_in[5];
    float* out = (float*)d_out;

    dim3 grid(N_ROWS, 3);
    icl_kernel<<<grid, BT>>>(a_gt, s_gt, e_gt, a_h, s_h, e_h, out);
}